// round 12
// baseline (speedup 1.0000x reference)
#include <cuda_runtime.h>
#include <cuda_bf16.h>
#include <math.h>

#define Bb 32
#define Ss 32
#define Nn 128
#define Uu 64
#define Ee 2
#define Ll 2
#define NSTEP 3
#define NC 5

// Scratch (allocation-free): h state and typed messages
__device__ float g_h[Bb * Nn * Uu];          // 1 MB
__device__ float g_M[Bb * Ee * Nn * Uu];     // 2 MB

// ---------------------------------------------------------------------------
// Gather: h0[b] = input_seq[b, clip(seq_lengths[b]-1, 0, S-1)]  (8192 floats)
// ---------------------------------------------------------------------------
__global__ void gather_kernel(const float* __restrict__ input_seq,
                              const int* __restrict__ seq_lengths) {
    int b = blockIdx.x;
    int idx = seq_lengths[b] - 1;
    if (idx < 0) idx = 0;
    if (idx > Ss - 1) idx = Ss - 1;
    const float* src = input_seq + ((size_t)b * Ss + idx) * (Nn * Uu);
    float* dst = g_h + (size_t)b * (Nn * Uu);
    for (int i = threadIdx.x * 4; i < Nn * Uu; i += blockDim.x * 4) {
        *(float4*)&dst[i] = *(const float4*)&src[i];
    }
}

// ---------------------------------------------------------------------------
// msgmm: M[b,e,tile*32 .. +31, :] = A[b,e,rows,:] @ h[b]   ([32,128]@[128,64])
// grid(4, E, B), 256 threads. Register-tiled 2x4 per thread.
// ---------------------------------------------------------------------------
__global__ void msgmm_kernel(const float* __restrict__ A) {
    int tile = blockIdx.x;   // 0..3  (32 rows each)
    int e    = blockIdx.y;
    int b    = blockIdx.z;

    __shared__ float sh[Nn][Uu];   // full h for this batch (32 KB)
    __shared__ float sA[32][32];   // A chunk (4 KB)

    int tid = threadIdx.x;
    int tx = tid & 15;             // col group (4 cols)
    int ty = tid >> 4;             // row group (2 rows)

    const float* hb = g_h + (size_t)b * Nn * Uu;
    for (int i = tid * 4; i < Nn * Uu; i += 1024)
        *(float4*)&sh[0][i] = *(const float4*)&hb[i];

    const float* Ab = A + (((size_t)b * Ee + e) * Nn + tile * 32) * Nn;

    float acc[2][4] = {};

    for (int kk = 0; kk < Nn; kk += 32) {
        __syncthreads();   // sh ready (first iter) / previous chunk consumed
        for (int i = tid; i < 32 * 32; i += 256) {
            int r = i >> 5, c = i & 31;
            sA[r][c] = Ab[(size_t)r * Nn + kk + c];
        }
        __syncthreads();
        #pragma unroll
        for (int k = 0; k < 32; k++) {
            float a0 = sA[ty * 2][k];
            float a1 = sA[ty * 2 + 1][k];
            float4 bv = *(const float4*)&sh[kk + k][tx * 4];
            acc[0][0] += a0 * bv.x; acc[0][1] += a0 * bv.y;
            acc[0][2] += a0 * bv.z; acc[0][3] += a0 * bv.w;
            acc[1][0] += a1 * bv.x; acc[1][1] += a1 * bv.y;
            acc[1][2] += a1 * bv.z; acc[1][3] += a1 * bv.w;
        }
    }

    float* Mout = g_M + (((size_t)b * Ee + e) * Nn + tile * 32) * Uu;
    #pragma unroll
    for (int rr = 0; rr < 2; rr++) {
        int row = ty * 2 + rr;
        float4 v = make_float4(acc[rr][0], acc[rr][1], acc[rr][2], acc[rr][3]);
        *(float4*)&Mout[(size_t)row * Uu + tx * 4] = v;
    }
}

// ---------------------------------------------------------------------------
// rowupdate: fully fused per-row GRU-style gate update.
//   a = M0@W0 + M1@W1 + b_msg
//   z = sig(a@Wg0 + h@Ug0 + bg0); r = sig(a@Wg1 + h@Ug1 + bg1)
//   c = tanh(a@Wg2 + (r*h)@Ug2 + bg2); h = (1-z)h + z c
// grid(8, B): 16 rows per block, 256 threads. Thread owns (row, 4 cols).
// ---------------------------------------------------------------------------
__global__ void rowupdate_kernel(const float* __restrict__ W_msg,
                                 const float* __restrict__ b_msg,
                                 const float* __restrict__ Wg,
                                 const float* __restrict__ Ug,
                                 const float* __restrict__ bg,
                                 int l) {
    int tile = blockIdx.x;   // 0..7
    int b    = blockIdx.y;

    __shared__ float sh[16][64];
    __shared__ float sM0[16][64];   // reused as rh buffer after 'a' phase
    __shared__ float sM1[16][64];
    __shared__ float sa[16][64];
    __shared__ float sW[64][64];

    int tid = threadIdx.x;
    int row = tid >> 4;      // 0..15
    int cg  = tid & 15;
    int col = cg * 4;
    int r0  = tile * 16;

    const float* hb = g_h + ((size_t)b * Nn + r0) * Uu;
    const float* M0 = g_M + (((size_t)b * Ee + 0) * Nn + r0) * Uu;
    const float* M1 = g_M + (((size_t)b * Ee + 1) * Nn + r0) * Uu;

    {
        int i = tid * 4;  // covers 0..1020, exactly all 1024 floats
        *(float4*)&sh[0][i]  = *(const float4*)&hb[i];
        *(float4*)&sM0[0][i] = *(const float4*)&M0[i];
        *(float4*)&sM1[0][i] = *(const float4*)&M1[i];
    }

    // stage one 64x64 weight matrix into sW (syncs protect prior readers
    // of sW and make freshly written tiles visible)
    auto loadW = [&](const float* src) {
        __syncthreads();
        for (int i = tid * 4; i < 4096; i += 1024)
            *(float4*)&sW[0][i] = *(const float4*)&src[i];
        __syncthreads();
    };

    auto gemm = [&](float* accv, const float (*X)[64]) {
        #pragma unroll 4
        for (int k = 0; k < 64; k++) {
            float x = X[row][k];
            float4 w = *(const float4*)&sW[k][col];
            accv[0] += x * w.x; accv[1] += x * w.y;
            accv[2] += x * w.z; accv[3] += x * w.w;
        }
    };

    // --- a = M0@W0 + M1@W1 + b_msg ---
    float acc[4] = {0.f, 0.f, 0.f, 0.f};
    loadW(W_msg + ((size_t)l * Ee + 0) * Uu * Uu);
    float4 h4 = *(const float4*)&sh[row][col];   // tiles visible after loadW sync
    gemm(acc, sM0);
    loadW(W_msg + ((size_t)l * Ee + 1) * Uu * Uu);
    gemm(acc, sM1);
    {
        float4 bm = *(const float4*)&b_msg[l * Uu + col];
        acc[0] += bm.x; acc[1] += bm.y; acc[2] += bm.z; acc[3] += bm.w;
        *(float4*)&sa[row][col] = make_float4(acc[0], acc[1], acc[2], acc[3]);
    }

    // --- z = sigmoid(a@Wg0 + h@Ug0 + bg0) ---
    float accz[4];
    {
        float4 bb = *(const float4*)&bg[((size_t)l * 3 + 0) * Uu + col];
        accz[0] = bb.x; accz[1] = bb.y; accz[2] = bb.z; accz[3] = bb.w;
    }
    loadW(Ug + ((size_t)l * 3 + 0) * Uu * Uu);   // sync also publishes sa
    gemm(accz, sh);
    loadW(Wg + ((size_t)l * 3 + 0) * Uu * Uu);
    gemm(accz, sa);
    float z[4];
    #pragma unroll
    for (int j = 0; j < 4; j++) z[j] = 1.0f / (1.0f + expf(-accz[j]));

    // --- r = sigmoid(a@Wg1 + h@Ug1 + bg1); rh = r*h (into sM0) ---
    float accr[4];
    {
        float4 bb = *(const float4*)&bg[((size_t)l * 3 + 1) * Uu + col];
        accr[0] = bb.x; accr[1] = bb.y; accr[2] = bb.z; accr[3] = bb.w;
    }
    loadW(Ug + ((size_t)l * 3 + 1) * Uu * Uu);
    gemm(accr, sh);
    loadW(Wg + ((size_t)l * 3 + 1) * Uu * Uu);
    gemm(accr, sa);
    {
        float r_[4];
        #pragma unroll
        for (int j = 0; j < 4; j++) r_[j] = 1.0f / (1.0f + expf(-accr[j]));
        float4 rh = make_float4(r_[0] * h4.x, r_[1] * h4.y, r_[2] * h4.z, r_[3] * h4.w);
        *(float4*)&sM0[row][col] = rh;
    }

    // --- c = tanh(a@Wg2 + rh@Ug2 + bg2) ---
    float accc[4];
    {
        float4 bb = *(const float4*)&bg[((size_t)l * 3 + 2) * Uu + col];
        accc[0] = bb.x; accc[1] = bb.y; accc[2] = bb.z; accc[3] = bb.w;
    }
    loadW(Ug + ((size_t)l * 3 + 2) * Uu * Uu);   // sync publishes rh in sM0
    gemm(accc, sM0);
    loadW(Wg + ((size_t)l * 3 + 2) * Uu * Uu);
    gemm(accc, sa);

    // --- h_new = (1-z)*h + z*c ---
    float hn[4];
    hn[0] = (1.0f - z[0]) * h4.x + z[0] * tanhf(accc[0]);
    hn[1] = (1.0f - z[1]) * h4.y + z[1] * tanhf(accc[1]);
    hn[2] = (1.0f - z[2]) * h4.z + z[2] * tanhf(accc[2]);
    hn[3] = (1.0f - z[3]) * h4.w + z[3] * tanhf(accc[3]);

    float* hout = g_h + ((size_t)b * Nn + r0 + row) * Uu + col;
    *(float4*)hout = make_float4(hn[0], hn[1], hn[2], hn[3]);
}

// ---------------------------------------------------------------------------
// final: logits[b,n,:] = relu(h[b,n,:]) @ fc_w + fc_b; out[b,:] = max over n
// grid(B), 128 threads (one per n).
// ---------------------------------------------------------------------------
__global__ void final_kernel(const float* __restrict__ fc_w,
                             const float* __restrict__ fc_b,
                             float* __restrict__ out) {
    int b = blockIdx.x;
    int n = threadIdx.x;   // 0..127

    __shared__ float sw[Uu * NC];
    __shared__ float slog[Nn][NC];

    for (int i = n; i < Uu * NC; i += 128) sw[i] = fc_w[i];
    __syncthreads();

    const float* hrow = g_h + ((size_t)b * Nn + n) * Uu;
    float acc[NC];
    #pragma unroll
    for (int c = 0; c < NC; c++) acc[c] = fc_b[c];
    for (int u = 0; u < Uu; u++) {
        float v = hrow[u];
        v = v > 0.f ? v : 0.f;
        #pragma unroll
        for (int c = 0; c < NC; c++) acc[c] += v * sw[u * NC + c];
    }
    #pragma unroll
    for (int c = 0; c < NC; c++) slog[n][c] = acc[c];
    __syncthreads();

    for (int s = 64; s > 0; s >>= 1) {
        if (n < s) {
            #pragma unroll
            for (int c = 0; c < NC; c++)
                slog[n][c] = fmaxf(slog[n][c], slog[n + s][c]);
        }
        __syncthreads();
    }
    if (n < NC) out[b * NC + n] = slog[0][n];
}

// ---------------------------------------------------------------------------
// Launch
// ---------------------------------------------------------------------------
extern "C" void kernel_launch(void* const* d_in, const int* in_sizes, int n_in,
                              void* d_out, int out_size) {
    const float* input_seq   = (const float*)d_in[0];  // (B,S,N*U)
    const int*   seq_lengths = (const int*)d_in[1];    // (B,)
    const float* Adj         = (const float*)d_in[2];  // (B,E,N,N)
    const float* W_msg       = (const float*)d_in[3];  // (L,E,U,U)
    const float* b_msg       = (const float*)d_in[4];  // (L,U)
    const float* Wg          = (const float*)d_in[5];  // (L,3,U,U)
    const float* Ug          = (const float*)d_in[6];  // (L,3,U,U)
    const float* bg          = (const float*)d_in[7];  // (L,3,U)
    const float* fc_w        = (const float*)d_in[8];  // (U,NC)
    const float* fc_b        = (const float*)d_in[9];  // (NC,)
    float* out = (float*)d_out;

    gather_kernel<<<Bb, 256>>>(input_seq, seq_lengths);

    for (int l = 0; l < Ll; l++) {
        for (int s = 0; s < NSTEP; s++) {
            msgmm_kernel<<<dim3(4, Ee, Bb), 256>>>(Adj);
            rowupdate_kernel<<<dim3(8, Bb), 256>>>(W_msg, b_msg, Wg, Ug, bg, l);
        }
    }

    final_kernel<<<Bb, 128>>>(fc_w, fc_b, out);
}

// round 13
// speedup vs baseline: 2.0900x; 2.0900x over previous
#include <cuda_runtime.h>
#include <cuda_bf16.h>
#include <math.h>

// Problem constants
// B=32, S=32, N=128, U=64, E=2, L=2, N_STEPS=3, NC=5

// Scratch (allocation-free)
__device__ float g_h[32 * 128 * 64];     // hidden state, per batch
__device__ float g_part[32 * 4 * 5];     // per-CTA partial logit maxima

// smem layout (float offsets)
#define OFF_SHF 0                         // full h  [128][64]           8192
#define OFF_SA  8192                      // A slice [2][32][132]        8448
#define OFF_SM0 16640                     // M0 tile [32][68]            2176
#define OFF_SM1 18816                     // M1 tile [32][68]            2176
#define OFF_SAa 20992                     // a tile  [32][68]            2176
#define OFF_SW0 23168                     // weight buf 0 [64][64]       4096
#define OFF_SW1 27264                     // weight buf 1 [64][64]       4096
#define SMEM_FLOATS 31360
#define SMEM_BYTES (SMEM_FLOATS * 4)

__device__ __forceinline__ void cpa16(float* s, const float* g) {
    unsigned a = (unsigned)__cvta_generic_to_shared(s);
    asm volatile("cp.async.cg.shared.global [%0], [%1], 16;" :: "r"(a), "l"(g));
}
#define CP_COMMIT() asm volatile("cp.async.commit_group;" ::: "memory")
#define CP_WAIT(n)  asm volatile("cp.async.wait_group %0;" :: "n"(n) : "memory")

// prefetch one 64x64 fp32 weight matrix into smem (all 256 threads), 1 group
__device__ __forceinline__ void prefW(float* dst, const float* src, int tid) {
    #pragma unroll
    for (int i = 0; i < 4; i++) {
        int o = (tid + i * 256) * 4;
        cpa16(dst + o, src + o);
    }
    CP_COMMIT();
}

__device__ __forceinline__ void cl_sync() {
    asm volatile("barrier.cluster.arrive.aligned;" ::: "memory");
    asm volatile("barrier.cluster.wait.aligned;" ::: "memory");
}

// acc[2][4] += X(2 rows) @ W ; x0/x1 are row base pointers (any stride)
__device__ __forceinline__ void gemm8(float (&acc)[2][4],
                                      const float* __restrict__ x0,
                                      const float* __restrict__ x1,
                                      const float* __restrict__ W, int col) {
    #pragma unroll 8
    for (int k = 0; k < 64; k++) {
        float a0 = x0[k], a1 = x1[k];
        float4 w = *(const float4*)&W[k * 64 + col];
        acc[0][0] += a0 * w.x; acc[0][1] += a0 * w.y;
        acc[0][2] += a0 * w.z; acc[0][3] += a0 * w.w;
        acc[1][0] += a1 * w.x; acc[1][1] += a1 * w.y;
        acc[1][2] += a1 * w.z; acc[1][3] += a1 * w.w;
    }
}

__device__ __forceinline__ void bias2(float (&acc)[2][4], const float* b, int col) {
    float4 v = *(const float4*)&b[col];
    acc[0][0] = v.x; acc[0][1] = v.y; acc[0][2] = v.z; acc[0][3] = v.w;
    acc[1][0] = v.x; acc[1][1] = v.y; acc[1][2] = v.z; acc[1][3] = v.w;
}

__device__ __forceinline__ float sigf(float x) { return 1.0f / (1.0f + expf(-x)); }

__global__ void __cluster_dims__(4, 1, 1) __launch_bounds__(256, 1)
ggnn_all(const float* __restrict__ input_seq,
         const int* __restrict__ seq_lengths,
         const float* __restrict__ Adj,
         const float* __restrict__ W_msg,
         const float* __restrict__ b_msg,
         const float* __restrict__ Wg,
         const float* __restrict__ Ug,
         const float* __restrict__ bg,
         const float* __restrict__ fc_w,
         const float* __restrict__ fc_b,
         float* __restrict__ out)
{
    extern __shared__ float sm[];
    float* shf = sm + OFF_SHF;
    float* sA  = sm + OFF_SA;
    float* sM0 = sm + OFF_SM0;
    float* sM1 = sm + OFF_SM1;
    float* sa  = sm + OFF_SAa;
    float* sW0 = sm + OFF_SW0;
    float* sW1 = sm + OFF_SW1;

    const int tid   = threadIdx.x;
    const int rg    = tid >> 4;          // 0..15 -> rows rg, rg+16
    const int col   = (tid & 15) * 4;    // 4 cols
    const int b     = blockIdx.x >> 2;   // batch = cluster
    const int crank = blockIdx.x & 3;    // CTA rank in cluster
    const int r0    = crank * 32;        // this CTA's 32 rows

    // ---------------- prologue: gather h0 slice -> g_h, stage A slice -----
    {
        int idx = seq_lengths[b] - 1;
        idx = idx < 0 ? 0 : (idx > 31 ? 31 : idx);
        const float4* src = (const float4*)(input_seq +
                            ((size_t)(b * 32 + idx)) * 8192 + (size_t)r0 * 64);
        float4* dst = (float4*)(g_h + (size_t)b * 8192 + (size_t)r0 * 64);
        #pragma unroll
        for (int i = 0; i < 2; i++)
            __stcg(&dst[tid + i * 256], src[tid + i * 256]);

        // A[b][e][r0+r][:] -> sA[(e*32+r)*132 + k]  (padded stride, 16B aligned)
        #pragma unroll
        for (int i = 0; i < 8; i++) {
            int i4 = tid + i * 256;          // 0..2047 float4 index
            int e  = i4 >> 10;
            int r  = (i4 >> 5) & 31;
            int c4 = i4 & 31;
            float4 v = *(const float4*)(Adj +
                       (((size_t)b * 2 + e) * 128 + r0 + r) * 128 + c4 * 4);
            *(float4*)&sA[(e * 32 + r) * 132 + c4 * 4] = v;
        }
    }

    float4 hn0, hn1;   // final h for this thread's (rows rg, rg+16) x 4 cols

    for (int l = 0; l < 2; l++) {
        const float* Wm0 = W_msg + (size_t)l * 2 * 4096;
        const float* Wm1 = Wm0 + 4096;
        const float* Ugl = Ug + (size_t)l * 3 * 4096;
        const float* Wgl = Wg + (size_t)l * 3 * 4096;
        const float* bml = b_msg + l * 64;
        const float* bgl = bg + l * 192;

        for (int s = 0; s < 3; s++) {
            // -------- h exchange across cluster --------
            __threadfence();
            cl_sync();
            __threadfence();

            prefW(sW0, Wm0, tid);                      // G1
            prefW(sW1, Wm1, tid);                      // G2

            {   // read full h[b] (all 128 rows) into smem
                const float4* hb = (const float4*)(g_h + (size_t)b * 8192);
                float4* d = (float4*)shf;
                #pragma unroll
                for (int i = 0; i < 8; i++)
                    d[tid + i * 256] = __ldcg(&hb[tid + i * 256]);
            }
            __syncthreads();                            // shf visible

            // -------- msgmm: M_e = A_e @ h  (rows r0..r0+31) --------
            {
                float acc[2][2][4] = {};
                #pragma unroll 4
                for (int k = 0; k < 128; k++) {
                    float4 hv = *(const float4*)&shf[k * 64 + col];
                    float a00 = sA[rg * 132 + k];            // e0, row rg
                    float a01 = sA[(32 + rg) * 132 + k];     // e1, row rg
                    float a10 = sA[(rg + 16) * 132 + k];     // e0, row rg+16
                    float a11 = sA[(48 + rg) * 132 + k];     // e1, row rg+16
                    acc[0][0][0] += a00 * hv.x; acc[0][0][1] += a00 * hv.y;
                    acc[0][0][2] += a00 * hv.z; acc[0][0][3] += a00 * hv.w;
                    acc[0][1][0] += a01 * hv.x; acc[0][1][1] += a01 * hv.y;
                    acc[0][1][2] += a01 * hv.z; acc[0][1][3] += a01 * hv.w;
                    acc[1][0][0] += a10 * hv.x; acc[1][0][1] += a10 * hv.y;
                    acc[1][0][2] += a10 * hv.z; acc[1][0][3] += a10 * hv.w;
                    acc[1][1][0] += a11 * hv.x; acc[1][1][1] += a11 * hv.y;
                    acc[1][1][2] += a11 * hv.z; acc[1][1][3] += a11 * hv.w;
                }
                *(float4*)&sM0[rg * 68 + col] =
                    make_float4(acc[0][0][0], acc[0][0][1], acc[0][0][2], acc[0][0][3]);
                *(float4*)&sM1[rg * 68 + col] =
                    make_float4(acc[0][1][0], acc[0][1][1], acc[0][1][2], acc[0][1][3]);
                *(float4*)&sM0[(rg + 16) * 68 + col] =
                    make_float4(acc[1][0][0], acc[1][0][1], acc[1][0][2], acc[1][0][3]);
                *(float4*)&sM1[(rg + 16) * 68 + col] =
                    make_float4(acc[1][1][0], acc[1][1][1], acc[1][1][2], acc[1][1][3]);
            }
            CP_WAIT(1); __syncthreads();                // sM visible, W0 ready

            const float* hx0 = &shf[(r0 + rg) * 64];
            const float* hx1 = &shf[(r0 + rg + 16) * 64];
            float4 h0v = *(const float4*)&shf[(r0 + rg) * 64 + col];
            float4 h1v = *(const float4*)&shf[(r0 + rg + 16) * 64 + col];

            // -------- a = M0@W0 + M1@W1 + b_msg --------
            float accA[2][4];
            bias2(accA, bml, col);
            gemm8(accA, &sM0[rg * 68], &sM0[(rg + 16) * 68], sW0, col);
            __syncthreads();  prefW(sW0, Ugl, tid);     // G3 (Ug0)
            CP_WAIT(1); __syncthreads();                // W1 ready
            gemm8(accA, &sM1[rg * 68], &sM1[(rg + 16) * 68], sW1, col);
            *(float4*)&sa[rg * 68 + col] =
                make_float4(accA[0][0], accA[0][1], accA[0][2], accA[0][3]);
            *(float4*)&sa[(rg + 16) * 68 + col] =
                make_float4(accA[1][0], accA[1][1], accA[1][2], accA[1][3]);
            __syncthreads();  prefW(sW1, Wgl, tid);     // G4 (Wg0)
            CP_WAIT(1); __syncthreads();                // Ug0 ready, sa visible

            // -------- z = sigmoid(a@Wg0 + h@Ug0 + bg0) --------
            float accZ[2][4];
            bias2(accZ, bgl, col);
            gemm8(accZ, hx0, hx1, sW0, col);
            __syncthreads();  prefW(sW0, Ugl + 4096, tid);   // G5 (Ug1)
            CP_WAIT(1); __syncthreads();                     // Wg0 ready
            gemm8(accZ, &sa[rg * 68], &sa[(rg + 16) * 68], sW1, col);
            float z[2][4];
            #pragma unroll
            for (int j = 0; j < 4; j++) { z[0][j] = sigf(accZ[0][j]); z[1][j] = sigf(accZ[1][j]); }
            __syncthreads();  prefW(sW1, Wgl + 4096, tid);   // G6 (Wg1)
            CP_WAIT(1); __syncthreads();                     // Ug1 ready

            // -------- r = sigmoid(a@Wg1 + h@Ug1 + bg1); rh = r*h --------
            float accR[2][4];
            bias2(accR, bgl + 64, col);
            gemm8(accR, hx0, hx1, sW0, col);
            __syncthreads();  prefW(sW0, Ugl + 8192, tid);   // G7 (Ug2)
            CP_WAIT(1); __syncthreads();                     // Wg1 ready
            gemm8(accR, &sa[rg * 68], &sa[(rg + 16) * 68], sW1, col);
            {
                float r00 = sigf(accR[0][0]), r01 = sigf(accR[0][1]);
                float r02 = sigf(accR[0][2]), r03 = sigf(accR[0][3]);
                float r10 = sigf(accR[1][0]), r11 = sigf(accR[1][1]);
                float r12 = sigf(accR[1][2]), r13 = sigf(accR[1][3]);
                *(float4*)&sM0[rg * 68 + col] =
                    make_float4(r00 * h0v.x, r01 * h0v.y, r02 * h0v.z, r03 * h0v.w);
                *(float4*)&sM0[(rg + 16) * 68 + col] =
                    make_float4(r10 * h1v.x, r11 * h1v.y, r12 * h1v.z, r13 * h1v.w);
            }
            __syncthreads();  prefW(sW1, Wgl + 8192, tid);   // G8 (Wg2)
            CP_WAIT(1); __syncthreads();                     // Ug2 ready, rh visible

            // -------- c = tanh(a@Wg2 + rh@Ug2 + bg2); h = (1-z)h + z c ----
            float accC[2][4];
            bias2(accC, bgl + 128, col);
            gemm8(accC, &sM0[rg * 68], &sM0[(rg + 16) * 68], sW0, col);
            CP_WAIT(0); __syncthreads();                     // Wg2 ready
            gemm8(accC, &sa[rg * 68], &sa[(rg + 16) * 68], sW1, col);

            hn0 = make_float4(
                (1.0f - z[0][0]) * h0v.x + z[0][0] * tanhf(accC[0][0]),
                (1.0f - z[0][1]) * h0v.y + z[0][1] * tanhf(accC[0][1]),
                (1.0f - z[0][2]) * h0v.z + z[0][2] * tanhf(accC[0][2]),
                (1.0f - z[0][3]) * h0v.w + z[0][3] * tanhf(accC[0][3]));
            hn1 = make_float4(
                (1.0f - z[1][0]) * h1v.x + z[1][0] * tanhf(accC[1][0]),
                (1.0f - z[1][1]) * h1v.y + z[1][1] * tanhf(accC[1][1]),
                (1.0f - z[1][2]) * h1v.z + z[1][2] * tanhf(accC[1][2]),
                (1.0f - z[1][3]) * h1v.w + z[1][3] * tanhf(accC[1][3]));

            float* hb = g_h + (size_t)b * 8192;
            __stcg((float4*)&hb[(r0 + rg) * 64 + col], hn0);
            __stcg((float4*)&hb[(r0 + rg + 16) * 64 + col], hn1);
        }
    }

    // ---------------- final: relu -> fc -> max over nodes -----------------
    __syncthreads();                     // drain all smem readers
    *(float4*)&sa[rg * 68 + col] = hn0;  // reuse sa as final-h tile
    *(float4*)&sa[(rg + 16) * 68 + col] = hn1;
    for (int i = tid; i < 320; i += 256) sW0[i] = fc_w[i];
    __syncthreads();

    if (tid < 160) {
        int row = tid / 5, c = tid % 5;
        float acc = fc_b[c];
        #pragma unroll 8
        for (int u = 0; u < 64; u++) {
            float v = sa[row * 68 + u];
            v = v > 0.0f ? v : 0.0f;
            acc += v * sW0[u * 5 + c];
        }
        sM1[row * 5 + c] = acc;          // per-row logits
    }
    __syncthreads();
    if (tid < 5) {
        float m = -1e30f;
        #pragma unroll 8
        for (int r = 0; r < 32; r++) m = fmaxf(m, sM1[r * 5 + tid]);
        __stcg(&g_part[(b * 4 + crank) * 5 + tid], m);
    }
    __threadfence();
    cl_sync();
    __threadfence();
    if (crank == 0 && tid < 5) {
        float m = -1e30f;
        #pragma unroll
        for (int r = 0; r < 4; r++)
            m = fmaxf(m, __ldcg(&g_part[(b * 4 + r) * 5 + tid]));
        out[b * 5 + tid] = m;
    }
}

// ---------------------------------------------------------------------------
extern "C" void kernel_launch(void* const* d_in, const int* in_sizes, int n_in,
                              void* d_out, int out_size) {
    const float* input_seq   = (const float*)d_in[0];
    const int*   seq_lengths = (const int*)d_in[1];
    const float* Adj         = (const float*)d_in[2];
    const float* W_msg       = (const float*)d_in[3];
    const float* b_msg       = (const float*)d_in[4];
    const float* Wg          = (const float*)d_in[5];
    const float* Ug          = (const float*)d_in[6];
    const float* bg          = (const float*)d_in[7];
    const float* fc_w        = (const float*)d_in[8];
    const float* fc_b        = (const float*)d_in[9];
    float* out = (float*)d_out;

    cudaFuncSetAttribute(ggnn_all,
                         cudaFuncAttributeMaxDynamicSharedMemorySize, SMEM_BYTES);

    ggnn_all<<<128, 256, SMEM_BYTES>>>(input_seq, seq_lengths, Adj,
                                       W_msg, b_msg, Wg, Ug, bg,
                                       fc_w, fc_b, out);
}

// round 14
// speedup vs baseline: 2.0939x; 1.0019x over previous
#include <cuda_runtime.h>
#include <cuda_bf16.h>
#include <math.h>

// Problem constants
// B=32, S=32, N=128, U=64, E=2, L=2, N_STEPS=3, NC=5

// Scratch (allocation-free)
__device__ float g_h[32 * 128 * 64];     // hidden state, per batch
__device__ float g_part[32 * 4 * 5];     // per-CTA partial logit maxima

// smem layout (float offsets)
#define OFF_SHF 0                         // full h  [128][64]           8192
#define OFF_SA  8192                      // A slice [2][32][132]        8448
#define OFF_SM0 16640                     // M0 tile [32][68]            2176
#define OFF_SM1 18816                     // M1 tile [32][68]            2176
#define OFF_SAa 20992                     // a tile  [32][68]            2176
#define OFF_SW0 23168                     // weight buf 0 [64][64]       4096
#define OFF_SW1 27264                     // weight buf 1 [64][64]       4096
#define SMEM_FLOATS 31360
#define SMEM_BYTES (SMEM_FLOATS * 4)

__device__ __forceinline__ void cpa16(float* s, const float* g) {
    unsigned a = (unsigned)__cvta_generic_to_shared(s);
    asm volatile("cp.async.cg.shared.global [%0], [%1], 16;" :: "r"(a), "l"(g));
}
#define CP_COMMIT() asm volatile("cp.async.commit_group;" ::: "memory")
#define CP_WAIT(n)  asm volatile("cp.async.wait_group %0;" :: "n"(n) : "memory")

// prefetch one 64x64 fp32 weight matrix into smem (all 256 threads), 1 group
__device__ __forceinline__ void prefW(float* dst, const float* src, int tid) {
    #pragma unroll
    for (int i = 0; i < 4; i++) {
        int o = (tid + i * 256) * 4;
        cpa16(dst + o, src + o);
    }
    CP_COMMIT();
}

__device__ __forceinline__ void cl_sync() {
    asm volatile("barrier.cluster.arrive.aligned;" ::: "memory");
    asm volatile("barrier.cluster.wait.aligned;" ::: "memory");
}

// acc[2][4] += X(2 rows) @ W ; x0/x1 are row base pointers (any stride)
__device__ __forceinline__ void gemm8(float (&acc)[2][4],
                                      const float* __restrict__ x0,
                                      const float* __restrict__ x1,
                                      const float* __restrict__ W, int col) {
    #pragma unroll 8
    for (int k = 0; k < 64; k++) {
        float a0 = x0[k], a1 = x1[k];
        float4 w = *(const float4*)&W[k * 64 + col];
        acc[0][0] += a0 * w.x; acc[0][1] += a0 * w.y;
        acc[0][2] += a0 * w.z; acc[0][3] += a0 * w.w;
        acc[1][0] += a1 * w.x; acc[1][1] += a1 * w.y;
        acc[1][2] += a1 * w.z; acc[1][3] += a1 * w.w;
    }
}

__device__ __forceinline__ void bias2(float (&acc)[2][4], const float* b, int col) {
    float4 v = *(const float4*)&b[col];
    acc[0][0] = v.x; acc[0][1] = v.y; acc[0][2] = v.z; acc[0][3] = v.w;
    acc[1][0] = v.x; acc[1][1] = v.y; acc[1][2] = v.z; acc[1][3] = v.w;
}

__device__ __forceinline__ float sigf(float x) { return 1.0f / (1.0f + expf(-x)); }

__global__ void __cluster_dims__(4, 1, 1) __launch_bounds__(256, 1)
ggnn_all(const float* __restrict__ input_seq,
         const int* __restrict__ seq_lengths,
         const float* __restrict__ Adj,
         const float* __restrict__ W_msg,
         const float* __restrict__ b_msg,
         const float* __restrict__ Wg,
         const float* __restrict__ Ug,
         const float* __restrict__ bg,
         const float* __restrict__ fc_w,
         const float* __restrict__ fc_b,
         float* __restrict__ out)
{
    extern __shared__ float sm[];
    float* shf = sm + OFF_SHF;
    float* sA  = sm + OFF_SA;
    float* sM0 = sm + OFF_SM0;
    float* sM1 = sm + OFF_SM1;
    float* sa  = sm + OFF_SAa;
    float* sW0 = sm + OFF_SW0;
    float* sW1 = sm + OFF_SW1;

    const int tid   = threadIdx.x;
    const int rg    = tid >> 4;          // 0..15 -> rows rg, rg+16
    const int col   = (tid & 15) * 4;    // 4 cols
    const int b     = blockIdx.x >> 2;   // batch = cluster
    const int crank = blockIdx.x & 3;    // CTA rank in cluster
    const int r0    = crank * 32;        // this CTA's 32 rows

    // ---------------- prologue: gather h0 slice -> g_h, stage A slice -----
    {
        int idx = seq_lengths[b] - 1;
        idx = idx < 0 ? 0 : (idx > 31 ? 31 : idx);
        const float4* src = (const float4*)(input_seq +
                            ((size_t)(b * 32 + idx)) * 8192 + (size_t)r0 * 64);
        float4* dst = (float4*)(g_h + (size_t)b * 8192 + (size_t)r0 * 64);
        #pragma unroll
        for (int i = 0; i < 2; i++)
            __stcg(&dst[tid + i * 256], src[tid + i * 256]);

        // A[b][e][r0+r][:] -> sA[(e*32+r)*132 + k]  (padded stride, 16B aligned)
        #pragma unroll
        for (int i = 0; i < 8; i++) {
            int i4 = tid + i * 256;          // 0..2047 float4 index
            int e  = i4 >> 10;
            int r  = (i4 >> 5) & 31;
            int c4 = i4 & 31;
            float4 v = *(const float4*)(Adj +
                       (((size_t)b * 2 + e) * 128 + r0 + r) * 128 + c4 * 4);
            *(float4*)&sA[(e * 32 + r) * 132 + c4 * 4] = v;
        }
    }

    float4 hn0, hn1;   // final h for this thread's (rows rg, rg+16) x 4 cols

    for (int l = 0; l < 2; l++) {
        const float* Wm0 = W_msg + (size_t)l * 2 * 4096;
        const float* Wm1 = Wm0 + 4096;
        const float* Ugl = Ug + (size_t)l * 3 * 4096;
        const float* Wgl = Wg + (size_t)l * 3 * 4096;
        const float* bml = b_msg + l * 64;
        const float* bgl = bg + l * 192;

        for (int s = 0; s < 3; s++) {
            // -------- h exchange across cluster --------
            __threadfence();
            cl_sync();
            __threadfence();

            prefW(sW0, Wm0, tid);                      // G1
            prefW(sW1, Wm1, tid);                      // G2

            {   // read full h[b] (all 128 rows) into smem
                const float4* hb = (const float4*)(g_h + (size_t)b * 8192);
                float4* d = (float4*)shf;
                #pragma unroll
                for (int i = 0; i < 8; i++)
                    d[tid + i * 256] = __ldcg(&hb[tid + i * 256]);
            }
            __syncthreads();                            // shf visible

            // -------- msgmm: M_e = A_e @ h  (rows r0..r0+31) --------
            {
                float acc[2][2][4] = {};
                #pragma unroll 4
                for (int k = 0; k < 128; k++) {
                    float4 hv = *(const float4*)&shf[k * 64 + col];
                    float a00 = sA[rg * 132 + k];            // e0, row rg
                    float a01 = sA[(32 + rg) * 132 + k];     // e1, row rg
                    float a10 = sA[(rg + 16) * 132 + k];     // e0, row rg+16
                    float a11 = sA[(48 + rg) * 132 + k];     // e1, row rg+16
                    acc[0][0][0] += a00 * hv.x; acc[0][0][1] += a00 * hv.y;
                    acc[0][0][2] += a00 * hv.z; acc[0][0][3] += a00 * hv.w;
                    acc[0][1][0] += a01 * hv.x; acc[0][1][1] += a01 * hv.y;
                    acc[0][1][2] += a01 * hv.z; acc[0][1][3] += a01 * hv.w;
                    acc[1][0][0] += a10 * hv.x; acc[1][0][1] += a10 * hv.y;
                    acc[1][0][2] += a10 * hv.z; acc[1][0][3] += a10 * hv.w;
                    acc[1][1][0] += a11 * hv.x; acc[1][1][1] += a11 * hv.y;
                    acc[1][1][2] += a11 * hv.z; acc[1][1][3] += a11 * hv.w;
                }
                *(float4*)&sM0[rg * 68 + col] =
                    make_float4(acc[0][0][0], acc[0][0][1], acc[0][0][2], acc[0][0][3]);
                *(float4*)&sM1[rg * 68 + col] =
                    make_float4(acc[0][1][0], acc[0][1][1], acc[0][1][2], acc[0][1][3]);
                *(float4*)&sM0[(rg + 16) * 68 + col] =
                    make_float4(acc[1][0][0], acc[1][0][1], acc[1][0][2], acc[1][0][3]);
                *(float4*)&sM1[(rg + 16) * 68 + col] =
                    make_float4(acc[1][1][0], acc[1][1][1], acc[1][1][2], acc[1][1][3]);
            }
            CP_WAIT(1); __syncthreads();                // sM visible, W0 ready

            const float* hx0 = &shf[(r0 + rg) * 64];
            const float* hx1 = &shf[(r0 + rg + 16) * 64];
            float4 h0v = *(const float4*)&shf[(r0 + rg) * 64 + col];
            float4 h1v = *(const float4*)&shf[(r0 + rg + 16) * 64 + col];

            // -------- a = M0@W0 + M1@W1 + b_msg --------
            float accA[2][4];
            bias2(accA, bml, col);
            gemm8(accA, &sM0[rg * 68], &sM0[(rg + 16) * 68], sW0, col);
            __syncthreads();  prefW(sW0, Ugl, tid);     // G3 (Ug0)
            CP_WAIT(1); __syncthreads();                // W1 ready
            gemm8(accA, &sM1[rg * 68], &sM1[(rg + 16) * 68], sW1, col);
            *(float4*)&sa[rg * 68 + col] =
                make_float4(accA[0][0], accA[0][1], accA[0][2], accA[0][3]);
            *(float4*)&sa[(rg + 16) * 68 + col] =
                make_float4(accA[1][0], accA[1][1], accA[1][2], accA[1][3]);
            __syncthreads();  prefW(sW1, Wgl, tid);     // G4 (Wg0)
            CP_WAIT(1); __syncthreads();                // Ug0 ready, sa visible

            // -------- z = sigmoid(a@Wg0 + h@Ug0 + bg0) --------
            float accZ[2][4];
            bias2(accZ, bgl, col);
            gemm8(accZ, hx0, hx1, sW0, col);
            __syncthreads();  prefW(sW0, Ugl + 4096, tid);   // G5 (Ug1)
            CP_WAIT(1); __syncthreads();                     // Wg0 ready
            gemm8(accZ, &sa[rg * 68], &sa[(rg + 16) * 68], sW1, col);
            float z[2][4];
            #pragma unroll
            for (int j = 0; j < 4; j++) { z[0][j] = sigf(accZ[0][j]); z[1][j] = sigf(accZ[1][j]); }
            __syncthreads();  prefW(sW1, Wgl + 4096, tid);   // G6 (Wg1)
            CP_WAIT(1); __syncthreads();                     // Ug1 ready

            // -------- r = sigmoid(a@Wg1 + h@Ug1 + bg1); rh = r*h --------
            float accR[2][4];
            bias2(accR, bgl + 64, col);
            gemm8(accR, hx0, hx1, sW0, col);
            __syncthreads();  prefW(sW0, Ugl + 8192, tid);   // G7 (Ug2)
            CP_WAIT(1); __syncthreads();                     // Wg1 ready
            gemm8(accR, &sa[rg * 68], &sa[(rg + 16) * 68], sW1, col);
            {
                float r00 = sigf(accR[0][0]), r01 = sigf(accR[0][1]);
                float r02 = sigf(accR[0][2]), r03 = sigf(accR[0][3]);
                float r10 = sigf(accR[1][0]), r11 = sigf(accR[1][1]);
                float r12 = sigf(accR[1][2]), r13 = sigf(accR[1][3]);
                *(float4*)&sM0[rg * 68 + col] =
                    make_float4(r00 * h0v.x, r01 * h0v.y, r02 * h0v.z, r03 * h0v.w);
                *(float4*)&sM0[(rg + 16) * 68 + col] =
                    make_float4(r10 * h1v.x, r11 * h1v.y, r12 * h1v.z, r13 * h1v.w);
            }
            __syncthreads();  prefW(sW1, Wgl + 8192, tid);   // G8 (Wg2)
            CP_WAIT(1); __syncthreads();                     // Ug2 ready, rh visible

            // -------- c = tanh(a@Wg2 + rh@Ug2 + bg2); h = (1-z)h + z c ----
            float accC[2][4];
            bias2(accC, bgl + 128, col);
            gemm8(accC, &sM0[rg * 68], &sM0[(rg + 16) * 68], sW0, col);
            CP_WAIT(0); __syncthreads();                     // Wg2 ready
            gemm8(accC, &sa[rg * 68], &sa[(rg + 16) * 68], sW1, col);

            hn0 = make_float4(
                (1.0f - z[0][0]) * h0v.x + z[0][0] * tanhf(accC[0][0]),
                (1.0f - z[0][1]) * h0v.y + z[0][1] * tanhf(accC[0][1]),
                (1.0f - z[0][2]) * h0v.z + z[0][2] * tanhf(accC[0][2]),
                (1.0f - z[0][3]) * h0v.w + z[0][3] * tanhf(accC[0][3]));
            hn1 = make_float4(
                (1.0f - z[1][0]) * h1v.x + z[1][0] * tanhf(accC[1][0]),
                (1.0f - z[1][1]) * h1v.y + z[1][1] * tanhf(accC[1][1]),
                (1.0f - z[1][2]) * h1v.z + z[1][2] * tanhf(accC[1][2]),
                (1.0f - z[1][3]) * h1v.w + z[1][3] * tanhf(accC[1][3]));

            float* hb = g_h + (size_t)b * 8192;
            __stcg((float4*)&hb[(r0 + rg) * 64 + col], hn0);
            __stcg((float4*)&hb[(r0 + rg + 16) * 64 + col], hn1);
        }
    }

    // ---------------- final: relu -> fc -> max over nodes -----------------
    __syncthreads();                     // drain all smem readers
    *(float4*)&sa[rg * 68 + col] = hn0;  // reuse sa as final-h tile
    *(float4*)&sa[(rg + 16) * 68 + col] = hn1;
    for (int i = tid; i < 320; i += 256) sW0[i] = fc_w[i];
    __syncthreads();

    if (tid < 160) {
        int row = tid / 5, c = tid % 5;
        float acc = fc_b[c];
        #pragma unroll 8
        for (int u = 0; u < 64; u++) {
            float v = sa[row * 68 + u];
            v = v > 0.0f ? v : 0.0f;
            acc += v * sW0[u * 5 + c];
        }
        sM1[row * 5 + c] = acc;          // per-row logits
    }
    __syncthreads();
    if (tid < 5) {
        float m = -1e30f;
        #pragma unroll 8
        for (int r = 0; r < 32; r++) m = fmaxf(m, sM1[r * 5 + tid]);
        __stcg(&g_part[(b * 4 + crank) * 5 + tid], m);
    }
    __threadfence();
    cl_sync();
    __threadfence();
    if (crank == 0 && tid < 5) {
        float m = -1e30f;
        #pragma unroll
        for (int r = 0; r < 4; r++)
            m = fmaxf(m, __ldcg(&g_part[(b * 4 + r) * 5 + tid]));
        out[b * 5 + tid] = m;
    }
}

// ---------------------------------------------------------------------------
extern "C" void kernel_launch(void* const* d_in, const int* in_sizes, int n_in,
                              void* d_out, int out_size) {
    const float* input_seq   = (const float*)d_in[0];
    const int*   seq_lengths = (const int*)d_in[1];
    const float* Adj         = (const float*)d_in[2];
    const float* W_msg       = (const float*)d_in[3];
    const float* b_msg       = (const float*)d_in[4];
    const float* Wg          = (const float*)d_in[5];
    const float* Ug          = (const float*)d_in[6];
    const float* bg          = (const float*)d_in[7];
    const float* fc_w        = (const float*)d_in[8];
    const float* fc_b        = (const float*)d_in[9];
    float* out = (float*)d_out;

    cudaFuncSetAttribute(ggnn_all,
                         cudaFuncAttributeMaxDynamicSharedMemorySize, SMEM_BYTES);

    ggnn_all<<<128, 256, SMEM_BYTES>>>(input_seq, seq_lengths, Adj,
                                       W_msg, b_msg, Wg, Ug, bg,
                                       fc_w, fc_b, out);
}